// round 2
// baseline (speedup 1.0000x reference)
#include <cuda_runtime.h>
#include <math.h>

#define SEQ 512
#define BB  64
#define EMB 512
#define HID 1024
#define NG  4096

typedef unsigned long long ull;

// ---------------- device scratch (no runtime allocation) ----------------
__device__ float d_gx[(size_t)SEQ * NG * BB];   // [s][n][b]  n = g*1024+j
__device__ float d_wxp[NG * EMB];               // packed Wx  [n][e]
__device__ float d_bxp[NG];
__device__ float d_whp[(size_t)NG * HID];       // packed Wh  [n][k]
__device__ float d_hbuf[2][BB * HID];           // ping-pong h   [b][k]
__device__ float d_cst[BB * HID];               // c state       [b][k]

// ---------------- f32x2 helpers ----------------
__device__ __forceinline__ void fma2(ull& d, ull a, ull b) {
    asm("fma.rn.f32x2 %0, %1, %2, %0;" : "+l"(d) : "l"(a), "l"(b));
}
__device__ __forceinline__ float hsum2(ull v) {
    unsigned lo = (unsigned)(v & 0xffffffffULL);
    unsigned hi = (unsigned)(v >> 32);
    return __uint_as_float(lo) + __uint_as_float(hi);
}
__device__ __forceinline__ float sigf(float x) {
    return 1.0f / (1.0f + __expf(-x));
}

// =====================================================================
// prepack: stack gate weights/biases gate-major, zero recurrent state.
// =====================================================================
__global__ void prepack_kernel(
    const float* __restrict__ W_ii, const float* __restrict__ b_ii, const float* __restrict__ W_hi,
    const float* __restrict__ W_if, const float* __restrict__ b_if, const float* __restrict__ W_hf,
    const float* __restrict__ W_ig, const float* __restrict__ b_ig, const float* __restrict__ W_hg,
    const float* __restrict__ W_io, const float* __restrict__ b_io, const float* __restrict__ W_ho)
{
    const int stride = gridDim.x * blockDim.x;
    const int tid = blockIdx.x * blockDim.x + threadIdx.x;

    for (int i = tid; i < NG * EMB; i += stride) {
        int n = i / EMB, k = i - n * EMB;
        int g = n >> 10, j = n & 1023;
        const float* w = (g == 0) ? W_ii : (g == 1) ? W_if : (g == 2) ? W_ig : W_io;
        d_wxp[i] = w[j * EMB + k];
    }
    for (int i = tid; i < NG * HID; i += stride) {
        int n = i >> 10, k = i & 1023;
        int g = n >> 10, j = n & 1023;
        const float* w = (g == 0) ? W_hi : (g == 1) ? W_hf : (g == 2) ? W_hg : W_ho;
        d_whp[i] = w[j * HID + k];
    }
    for (int i = tid; i < NG; i += stride) {
        int g = i >> 10, j = i & 1023;
        const float* b = (g == 0) ? b_ii : (g == 1) ? b_if : (g == 2) ? b_ig : b_io;
        d_bxp[i] = b[j];
    }
    for (int i = tid; i < BB * HID; i += stride) {
        d_hbuf[0][i] = 0.0f; d_hbuf[1][i] = 0.0f; d_cst[i] = 0.0f;
    }
}

// =====================================================================
// gx kernel: d_gx[s][n][b] = sum_e emb[x[b,s],e] * Wxp[n][e] + bxp[n]
// grid: (64 ntiles, 512 s), 256 threads. Tile 64n x 64b, K=512.
// k-pair-packed f32x2 accumulation; warp = (ksplit2 x bhalf2 x nhalf2),
// lane tile = 4n x 8b (accs packed over k-parity).
// =====================================================================
#define GX_CH 128
#define GX_AS 130          // smem row stride in words (8B-aligned rows)
#define GX_SMEM ((64 * GX_AS * 2) * 4)

__global__ void __launch_bounds__(256, 2) gx_kernel(const int* __restrict__ x,
                                                    const float* __restrict__ emb)
{
    extern __shared__ float sm[];
    float* shA = sm;                 // [64 b][130]
    float* shB = sm + 64 * GX_AS;    // [64 n][130]
    float* red = sm;                 // alias shA: [2 ks][64 n][64 b] = 32KB

    const int t = threadIdx.x;
    const int s = blockIdx.y;
    const int n0 = blockIdx.x * 64;

    __shared__ int tok[64];
    if (t < 64) tok[t] = x[t * SEQ + s];

    const int w = t >> 5, lane = t & 31;
    const int ks = w & 1, bh = (w >> 1) & 1, nh = w >> 2;
    const int ngrp = lane >> 2, bgrp = lane & 3;
    const int rbase = nh * 32 + ngrp * 4;
    const int bbase = bh * 32 + bgrp * 8;

    ull acc[4][8];
#pragma unroll
    for (int j = 0; j < 4; j++)
#pragma unroll
        for (int p = 0; p < 8; p++) acc[j][p] = 0ULL;

    for (int ch = 0; ch < EMB; ch += GX_CH) {
        __syncthreads();
        // stage A: 64 b x 128 k  (2048 float4)
#pragma unroll
        for (int i = 0; i < 8; i++) {
            int f = t + i * 256;
            int b = f >> 5, kq = (f & 31) * 4;
            float4 v = *(const float4*)(emb + (size_t)tok[b] * EMB + ch + kq);
            float* dst = shA + b * GX_AS + kq;
            *(float2*)(dst)     = make_float2(v.x, v.y);
            *(float2*)(dst + 2) = make_float2(v.z, v.w);
        }
        // stage B: 64 n x 128 k
#pragma unroll
        for (int i = 0; i < 8; i++) {
            int f = t + i * 256;
            int r = f >> 5, kq = (f & 31) * 4;
            float4 v = *(const float4*)(d_wxp + (size_t)(n0 + r) * EMB + ch + kq);
            float* dst = shB + r * GX_AS + kq;
            *(float2*)(dst)     = make_float2(v.x, v.y);
            *(float2*)(dst + 2) = make_float2(v.z, v.w);
        }
        __syncthreads();
        const int k0 = ks * 64;
#pragma unroll
        for (int kk = 0; kk < 32; kk++) {
            int kl = k0 + kk * 2;
            ull wv[4], av[8];
#pragma unroll
            for (int j = 0; j < 4; j++)
                wv[j] = *(const ull*)(shB + (rbase + j) * GX_AS + kl);
#pragma unroll
            for (int p = 0; p < 8; p++)
                av[p] = *(const ull*)(shA + (bbase + p) * GX_AS + kl);
#pragma unroll
            for (int j = 0; j < 4; j++)
#pragma unroll
                for (int p = 0; p < 8; p++)
                    fma2(acc[j][p], wv[j], av[p]);
        }
    }
    __syncthreads();
#pragma unroll
    for (int j = 0; j < 4; j++)
#pragma unroll
        for (int p = 0; p < 8; p++)
            red[ks * 4096 + (rbase + j) * 64 + (bbase + p)] = hsum2(acc[j][p]);
    __syncthreads();
#pragma unroll
    for (int i = 0; i < 16; i++) {
        int cell = t + i * 256;
        int r = cell >> 6, b = cell & 63;
        float v = red[r * 64 + b] + red[4096 + r * 64 + b] + d_bxp[n0 + r];
        d_gx[((size_t)s * NG + n0 + r) * BB + b] = v;
    }
}

// =====================================================================
// step kernel: one recurrent timestep.
// grid 128 CTAs (CTA owns j-range [j0, j0+8) across all 4 gates = 32 n rows,
// all 64 b), 256 threads. warp = (ksplit4 x bhalf2), lane tile 4n x 8b.
// =====================================================================
#define ST_CH 256
#define ST_RS 262          // smem row stride words
#define ST_SMEM (((64 + 32) * ST_RS) * 4)

__global__ void __launch_bounds__(256, 1) step_kernel(int s)
{
    extern __shared__ float sm[];
    float* shH = sm;                  // [64 b][262]
    float* shW = sm + 64 * ST_RS;     // [32 r][262]
    float* red = sm;                  // alias shH: [4 ks][32 r][64 b] = 32KB

    const float* __restrict__ hprev = d_hbuf[s & 1];
    float* __restrict__ hnext = d_hbuf[(s + 1) & 1];

    const int t = threadIdx.x;
    const int j0 = blockIdx.x * 8;

    const int w = t >> 5, lane = t & 31;
    const int ks = w & 3, bh = w >> 2;
    const int ngrp = lane >> 2, bgrp = lane & 3;
    const int rbase = ngrp * 4;
    const int bbase = bh * 32 + bgrp * 8;

    ull acc[4][8];
#pragma unroll
    for (int j = 0; j < 4; j++)
#pragma unroll
        for (int p = 0; p < 8; p++) acc[j][p] = 0ULL;

    for (int ch = 0; ch < HID; ch += ST_CH) {
        __syncthreads();
        // stage H: 64 b x 256 k  (4096 float4)
#pragma unroll
        for (int i = 0; i < 16; i++) {
            int f = t + i * 256;
            int b = f >> 6, kq = (f & 63) * 4;
            float4 v = *(const float4*)(hprev + b * HID + ch + kq);
            float* dst = shH + b * ST_RS + kq;
            *(float2*)(dst)     = make_float2(v.x, v.y);
            *(float2*)(dst + 2) = make_float2(v.z, v.w);
        }
        // stage W: 32 r x 256 k  (2048 float4);  r = g*8 + jj -> n = g*1024 + j0 + jj
#pragma unroll
        for (int i = 0; i < 8; i++) {
            int f = t + i * 256;
            int r = f >> 6, kq = (f & 63) * 4;
            int n = (r >> 3) * HID + j0 + (r & 7);
            float4 v = *(const float4*)(d_whp + (size_t)n * HID + ch + kq);
            float* dst = shW + r * ST_RS + kq;
            *(float2*)(dst)     = make_float2(v.x, v.y);
            *(float2*)(dst + 2) = make_float2(v.z, v.w);
        }
        __syncthreads();
        const int k0 = ks * 64;
#pragma unroll
        for (int kk = 0; kk < 32; kk++) {
            int kl = k0 + kk * 2;
            ull wv[4], hv[8];
#pragma unroll
            for (int j = 0; j < 4; j++)
                wv[j] = *(const ull*)(shW + (rbase + j) * ST_RS + kl);
#pragma unroll
            for (int p = 0; p < 8; p++)
                hv[p] = *(const ull*)(shH + (bbase + p) * ST_RS + kl);
#pragma unroll
            for (int j = 0; j < 4; j++)
#pragma unroll
                for (int p = 0; p < 8; p++)
                    fma2(acc[j][p], wv[j], hv[p]);
        }
    }
    __syncthreads();
#pragma unroll
    for (int j = 0; j < 4; j++)
#pragma unroll
        for (int p = 0; p < 8; p++)
            red[ks * 2048 + (rbase + j) * 64 + (bbase + p)] = hsum2(acc[j][p]);
    __syncthreads();

    // pointwise LSTM cell update: 8 j x 64 b cells
#pragma unroll
    for (int i = 0; i < 2; i++) {
        int cell = t + i * 256;
        int j = cell >> 6, b = cell & 63;
        float g[4];
#pragma unroll
        for (int gg = 0; gg < 4; gg++) {
            int r = gg * 8 + j;
            float v = red[r * 64 + b] + red[2048 + r * 64 + b]
                    + red[4096 + r * 64 + b] + red[6144 + r * 64 + b];
            v += d_gx[((size_t)s * NG + gg * 1024 + j0 + j) * BB + b];
            g[gg] = v;
        }
        float it = sigf(g[0]);
        float ft = sigf(g[1]);
        float gt = tanhf(g[2]);
        float ot = sigf(g[3]);
        int idx = b * HID + j0 + j;
        float c = ft * d_cst[idx] + it * gt;
        d_cst[idx] = c;
        hnext[idx] = ot * tanhf(c);
    }
}

// =====================================================================
// head: out = h @ V_w^T + V_b ; also emit h, c into d_out.
// d_out layout: [out(64x2), h(64x1024), c(64x1024)]
// =====================================================================
__global__ void head_kernel(const float* __restrict__ Vw, const float* __restrict__ Vb,
                            float* __restrict__ out)
{
    const float* hfin = d_hbuf[SEQ & 1];   // buffer written by step 511
    const int b = blockIdx.x, t = threadIdx.x;
    float s0 = 0.0f, s1 = 0.0f;
    for (int k = t; k < HID; k += 256) {
        float hv = hfin[b * HID + k];
        s0 += hv * Vw[k];
        s1 += hv * Vw[HID + k];
        out[128 + b * HID + k] = hv;
        out[128 + BB * HID + b * HID + k] = d_cst[b * HID + k];
    }
    __shared__ float r0[256], r1[256];
    r0[t] = s0; r1[t] = s1;
    __syncthreads();
    for (int off = 128; off > 0; off >>= 1) {
        if (t < off) { r0[t] += r0[t + off]; r1[t] += r1[t + off]; }
        __syncthreads();
    }
    if (t == 0) {
        out[b * 2 + 0] = r0[0] + Vb[0];
        out[b * 2 + 1] = r1[0] + Vb[1];
    }
}

// =====================================================================
extern "C" void kernel_launch(void* const* d_in, const int* in_sizes, int n_in,
                              void* d_out, int out_size)
{
    (void)in_sizes; (void)n_in; (void)out_size;
    const int*   x   = (const int*)d_in[0];
    const float* emb = (const float*)d_in[1];

    cudaFuncSetAttribute(gx_kernel,   cudaFuncAttributeMaxDynamicSharedMemorySize, GX_SMEM);
    cudaFuncSetAttribute(step_kernel, cudaFuncAttributeMaxDynamicSharedMemorySize, ST_SMEM);

    prepack_kernel<<<1024, 256>>>(
        (const float*)d_in[2],  (const float*)d_in[3],  (const float*)d_in[4],
        (const float*)d_in[5],  (const float*)d_in[6],  (const float*)d_in[7],
        (const float*)d_in[8],  (const float*)d_in[9],  (const float*)d_in[10],
        (const float*)d_in[11], (const float*)d_in[12], (const float*)d_in[13]);

    gx_kernel<<<dim3(64, 512), 256, GX_SMEM>>>(x, emb);

    for (int s = 0; s < SEQ; s++)
        step_kernel<<<128, 256, ST_SMEM>>>(s);

    head_kernel<<<BB, 256>>>((const float*)d_in[14], (const float*)d_in[15], (float*)d_out);
}

// round 3
// speedup vs baseline: 1.4137x; 1.4137x over previous
#include <cuda_runtime.h>
#include <math.h>

#define SEQ 512
#define BB  64
#define EMB 512
#define HID 1024
#define NG  4096

typedef unsigned long long ull;

// ---------------- device scratch (no runtime allocation) ----------------
__device__ float d_gx[(size_t)SEQ * NG * BB];   // [s][n][b]  n = g*1024+j
__device__ float d_wxp[NG * EMB];               // packed Wx  [n][e]
__device__ float d_bxp[NG];
__device__ float d_whp[(size_t)NG * HID];       // packed Wh  [n][k]
__device__ float d_hbuf[2][BB * HID];           // ping-pong h   [b][k]
__device__ float d_cst[BB * HID];               // c state       [b][k]
__device__ int   d_bar;                         // grid barrier counter

// ---------------- f32x2 helpers ----------------
__device__ __forceinline__ void fma2(ull& d, ull a, ull b) {
    asm("fma.rn.f32x2 %0, %1, %2, %0;" : "+l"(d) : "l"(a), "l"(b));
}
__device__ __forceinline__ float hsum2(ull v) {
    unsigned lo = (unsigned)(v & 0xffffffffULL);
    unsigned hi = (unsigned)(v >> 32);
    return __uint_as_float(lo) + __uint_as_float(hi);
}
__device__ __forceinline__ float sigf(float x) {
    return 1.0f / (1.0f + __expf(-x));
}

// =====================================================================
// prepack: stack gate weights/biases gate-major, zero recurrent state.
// =====================================================================
__global__ void prepack_kernel(
    const float* __restrict__ W_ii, const float* __restrict__ b_ii, const float* __restrict__ W_hi,
    const float* __restrict__ W_if, const float* __restrict__ b_if, const float* __restrict__ W_hf,
    const float* __restrict__ W_ig, const float* __restrict__ b_ig, const float* __restrict__ W_hg,
    const float* __restrict__ W_io, const float* __restrict__ b_io, const float* __restrict__ W_ho)
{
    const int stride = gridDim.x * blockDim.x;
    const int tid = blockIdx.x * blockDim.x + threadIdx.x;

    if (tid == 0) d_bar = 0;

    for (int i = tid; i < NG * EMB; i += stride) {
        int n = i / EMB, k = i - n * EMB;
        int g = n >> 10, j = n & 1023;
        const float* w = (g == 0) ? W_ii : (g == 1) ? W_if : (g == 2) ? W_ig : W_io;
        d_wxp[i] = w[j * EMB + k];
    }
    for (int i = tid; i < NG * HID; i += stride) {
        int n = i >> 10, k = i & 1023;
        int g = n >> 10, j = n & 1023;
        const float* w = (g == 0) ? W_hi : (g == 1) ? W_hf : (g == 2) ? W_hg : W_ho;
        d_whp[i] = w[j * HID + k];
    }
    for (int i = tid; i < NG; i += stride) {
        int g = i >> 10, j = i & 1023;
        const float* b = (g == 0) ? b_ii : (g == 1) ? b_if : (g == 2) ? b_ig : b_io;
        d_bxp[i] = b[j];
    }
    for (int i = tid; i < BB * HID; i += stride) {
        d_hbuf[0][i] = 0.0f; d_hbuf[1][i] = 0.0f; d_cst[i] = 0.0f;
    }
}

// =====================================================================
// gx kernel (unchanged from passing round): d_gx[s][n][b]
// =====================================================================
#define GX_CH 128
#define GX_AS 130
#define GX_SMEM ((64 * GX_AS * 2) * 4)

__global__ void __launch_bounds__(256, 2) gx_kernel(const int* __restrict__ x,
                                                    const float* __restrict__ emb)
{
    extern __shared__ float sm[];
    float* shA = sm;                 // [64 b][130]
    float* shB = sm + 64 * GX_AS;    // [64 n][130]
    float* red = sm;                 // alias: [2 ks][64 n][64 b]

    const int t = threadIdx.x;
    const int s = blockIdx.y;
    const int n0 = blockIdx.x * 64;

    __shared__ int tok[64];
    if (t < 64) tok[t] = x[t * SEQ + s];

    const int w = t >> 5, lane = t & 31;
    const int ks = w & 1, bh = (w >> 1) & 1, nh = w >> 2;
    const int ngrp = lane >> 2, bgrp = lane & 3;
    const int rbase = nh * 32 + ngrp * 4;
    const int bbase = bh * 32 + bgrp * 8;

    ull acc[4][8];
#pragma unroll
    for (int j = 0; j < 4; j++)
#pragma unroll
        for (int p = 0; p < 8; p++) acc[j][p] = 0ULL;

    for (int ch = 0; ch < EMB; ch += GX_CH) {
        __syncthreads();
#pragma unroll
        for (int i = 0; i < 8; i++) {
            int f = t + i * 256;
            int b = f >> 5, kq = (f & 31) * 4;
            float4 v = *(const float4*)(emb + (size_t)tok[b] * EMB + ch + kq);
            float* dst = shA + b * GX_AS + kq;
            *(float2*)(dst)     = make_float2(v.x, v.y);
            *(float2*)(dst + 2) = make_float2(v.z, v.w);
        }
#pragma unroll
        for (int i = 0; i < 8; i++) {
            int f = t + i * 256;
            int r = f >> 5, kq = (f & 31) * 4;
            float4 v = *(const float4*)(d_wxp + (size_t)(n0 + r) * EMB + ch + kq);
            float* dst = shB + r * GX_AS + kq;
            *(float2*)(dst)     = make_float2(v.x, v.y);
            *(float2*)(dst + 2) = make_float2(v.z, v.w);
        }
        __syncthreads();
        const int k0 = ks * 64;
#pragma unroll
        for (int kk = 0; kk < 32; kk++) {
            int kl = k0 + kk * 2;
            ull wv[4], av[8];
#pragma unroll
            for (int j = 0; j < 4; j++)
                wv[j] = *(const ull*)(shB + (rbase + j) * GX_AS + kl);
#pragma unroll
            for (int p = 0; p < 8; p++)
                av[p] = *(const ull*)(shA + (bbase + p) * GX_AS + kl);
#pragma unroll
            for (int j = 0; j < 4; j++)
#pragma unroll
                for (int p = 0; p < 8; p++)
                    fma2(acc[j][p], wv[j], av[p]);
        }
    }
    __syncthreads();
#pragma unroll
    for (int j = 0; j < 4; j++)
#pragma unroll
        for (int p = 0; p < 8; p++)
            red[ks * 4096 + (rbase + j) * 64 + (bbase + p)] = hsum2(acc[j][p]);
    __syncthreads();
#pragma unroll
    for (int i = 0; i < 16; i++) {
        int cell = t + i * 256;
        int r = cell >> 6, b = cell & 63;
        float v = red[r * 64 + b] + red[4096 + r * 64 + b] + d_bxp[n0 + r];
        d_gx[((size_t)s * NG + n0 + r) * BB + b] = v;
    }
}

// =====================================================================
// persistent recurrent kernel: all 512 timesteps in one launch.
// 128 CTAs x 256 threads, 1 CTA/SM (198KB smem), all co-resident.
// CTA owns j-range [j0, j0+8) across 4 gates = 32 W rows (in SMEM, staged
// ONCE), all 64 batch. warp = (ksplit4 x bhalf2); lane tile:
//   rows  r = ngrp + 8j      (ngrp = lane>>2, j = 0..3, so gate index = j)
//   batch b = bh*32 + bgrp + 4p (bgrp = lane&3, p = 0..7)
// f32x2 packing over k-pairs; LDS.128 loads 2 k-pairs. Row pitches chosen
// (mod 32 == 4) so every inner LDS is a single conflict-free wavefront.
// c state lives in registers for all 512 steps. Grid barrier between steps.
// =====================================================================
#define PS_WS 1028                 // W row pitch (words): mod32=4, 16B aligned
#define PS_HS 260                  // h row pitch (words): mod32=4, 16B aligned
#define PS_RS 68                   // red row pitch (words): mod32=4
#define PS_SMEM ((32 * PS_WS + 64 * PS_HS) * 4)

__global__ void __launch_bounds__(256, 1) persist_kernel()
{
    extern __shared__ float sm[];
    float* shW = sm;                  // [32 r][1028]
    float* shH = sm + 32 * PS_WS;     // [64 b][260]; aliased by red
    float* red = shH;                 // [4 ks][32 r][68]

    const int t = threadIdx.x;
    const int j0 = blockIdx.x * 8;
    const int w = t >> 5, lane = t & 31;
    const int ks = w & 3, bh = w >> 2;
    const int ngrp = lane >> 2, bgrp = lane & 3;

    // ---- stage W slice once: 32 rows x 1024 k (8192 float4) ----
#pragma unroll
    for (int i = 0; i < 32; i++) {
        int f = t + i * 256;
        int r = f >> 8, kq = (f & 255) << 2;
        int n = (r >> 3) * HID + j0 + (r & 7);   // gate = r>>3, jj = r&7
        float4 v = *(const float4*)(d_whp + (size_t)n * HID + kq);
        *(float4*)(shW + r * PS_WS + kq) = v;
    }

    float creg[2] = {0.0f, 0.0f};

    for (int s = 0; s < SEQ; s++) {
        const float* __restrict__ hprev = d_hbuf[s & 1];
        float* __restrict__ hnext = d_hbuf[(s + 1) & 1];

        ull acc[4][8];
#pragma unroll
        for (int j = 0; j < 4; j++)
#pragma unroll
            for (int p = 0; p < 8; p++) acc[j][p] = 0ULL;

        for (int ch = 0; ch < HID; ch += 256) {
            __syncthreads();
            // stage h chunk: 64 b x 256 k (4096 float4), L2 (bypass L1: cross-SM data)
#pragma unroll
            for (int i = 0; i < 16; i++) {
                int f = t + i * 256;
                int b = f >> 6, kq = (f & 63) << 2;
                float4 v = __ldcg((const float4*)(hprev + b * HID + ch + kq));
                *(float4*)(shH + b * PS_HS + kq) = v;
            }
            __syncthreads();
            const int k0 = ks * 64;
#pragma unroll
            for (int it = 0; it < 16; it++) {
                int kl = k0 + it * 4;          // 4 k values = 2 f32x2 pairs
                ulonglong2 wv[4], hv[8];
#pragma unroll
                for (int j = 0; j < 4; j++)
                    wv[j] = *(const ulonglong2*)(shW + (ngrp + j * 8) * PS_WS + ch + kl);
#pragma unroll
                for (int p = 0; p < 8; p++)
                    hv[p] = *(const ulonglong2*)(shH + (bh * 32 + bgrp + p * 4) * PS_HS + kl);
#pragma unroll
                for (int j = 0; j < 4; j++)
#pragma unroll
                    for (int p = 0; p < 8; p++) {
                        fma2(acc[j][p], wv[j].x, hv[p].x);
                        fma2(acc[j][p], wv[j].y, hv[p].y);
                    }
            }
        }
        __syncthreads();
        // ---- cross-warp k-split reduction through smem ----
#pragma unroll
        for (int j = 0; j < 4; j++)
#pragma unroll
            for (int p = 0; p < 8; p++) {
                int r = ngrp + j * 8;
                int b = bh * 32 + bgrp + p * 4;
                red[(ks * 32 + r) * PS_RS + b] = hsum2(acc[j][p]);
            }
        __syncthreads();

        // ---- pointwise LSTM cell update: 8 j x 64 b cells, 2 per thread ----
#pragma unroll
        for (int i = 0; i < 2; i++) {
            int cell = t + i * 256;
            int j = cell >> 6, b = cell & 63;
            float g[4];
#pragma unroll
            for (int gg = 0; gg < 4; gg++) {
                int r = gg * 8 + j;
                float v = red[r * PS_RS + b]
                        + red[(32 + r) * PS_RS + b]
                        + red[(64 + r) * PS_RS + b]
                        + red[(96 + r) * PS_RS + b];
                v += __ldg(&d_gx[((size_t)s * NG + gg * 1024 + j0 + j) * BB + b]);
                g[gg] = v;
            }
            float it_ = sigf(g[0]);
            float ft  = sigf(g[1]);
            float gt  = tanhf(g[2]);
            float ot  = sigf(g[3]);
            float c = ft * creg[i] + it_ * gt;
            creg[i] = c;
            hnext[b * HID + j0 + j] = ot * tanhf(c);
        }

        // ---- grid-wide barrier ----
        __threadfence();
        __syncthreads();
        if (t == 0) {
            atomicAdd(&d_bar, 1);
            const int target = 128 * (s + 1);
            while (*(volatile int*)&d_bar < target) { }
        }
        __syncthreads();
    }

    // ---- publish final c ----
#pragma unroll
    for (int i = 0; i < 2; i++) {
        int cell = t + i * 256;
        int j = cell >> 6, b = cell & 63;
        d_cst[b * HID + j0 + j] = creg[i];
    }
}

// =====================================================================
// head: out = h @ V_w^T + V_b ; also emit h, c into d_out.
// =====================================================================
__global__ void head_kernel(const float* __restrict__ Vw, const float* __restrict__ Vb,
                            float* __restrict__ out)
{
    const float* hfin = d_hbuf[SEQ & 1];
    const int b = blockIdx.x, t = threadIdx.x;
    float s0 = 0.0f, s1 = 0.0f;
    for (int k = t; k < HID; k += 256) {
        float hv = hfin[b * HID + k];
        s0 += hv * Vw[k];
        s1 += hv * Vw[HID + k];
        out[128 + b * HID + k] = hv;
        out[128 + BB * HID + b * HID + k] = d_cst[b * HID + k];
    }
    __shared__ float r0[256], r1[256];
    r0[t] = s0; r1[t] = s1;
    __syncthreads();
    for (int off = 128; off > 0; off >>= 1) {
        if (t < off) { r0[t] += r0[t + off]; r1[t] += r1[t + off]; }
        __syncthreads();
    }
    if (t == 0) {
        out[b * 2 + 0] = r0[0] + Vb[0];
        out[b * 2 + 1] = r1[0] + Vb[1];
    }
}

// =====================================================================
extern "C" void kernel_launch(void* const* d_in, const int* in_sizes, int n_in,
                              void* d_out, int out_size)
{
    (void)in_sizes; (void)n_in; (void)out_size;
    const int*   x   = (const int*)d_in[0];
    const float* emb = (const float*)d_in[1];

    cudaFuncSetAttribute(gx_kernel,      cudaFuncAttributeMaxDynamicSharedMemorySize, GX_SMEM);
    cudaFuncSetAttribute(persist_kernel, cudaFuncAttributeMaxDynamicSharedMemorySize, PS_SMEM);

    prepack_kernel<<<1024, 256>>>(
        (const float*)d_in[2],  (const float*)d_in[3],  (const float*)d_in[4],
        (const float*)d_in[5],  (const float*)d_in[6],  (const float*)d_in[7],
        (const float*)d_in[8],  (const float*)d_in[9],  (const float*)d_in[10],
        (const float*)d_in[11], (const float*)d_in[12], (const float*)d_in[13]);

    gx_kernel<<<dim3(64, 512), 256, GX_SMEM>>>(x, emb);

    persist_kernel<<<128, 256, PS_SMEM>>>();

    head_kernel<<<BB, 256>>>((const float*)d_in[14], (const float*)d_in[15], (float*)d_out);
}

// round 4
// speedup vs baseline: 1.6305x; 1.1534x over previous
#include <cuda_runtime.h>
#include <math.h>

#define SEQ 512
#define BB  64
#define EMB 512
#define HID 1024
#define NG  4096

typedef unsigned long long ull;

// ---------------- device scratch (no runtime allocation) ----------------
__device__ float d_gx[(size_t)SEQ * NG * BB];   // [s][n][b]  n = g*1024+j
__device__ float d_wxp[NG * EMB];               // packed Wx  [n][e]
__device__ float d_bxp[NG];
__device__ float d_whp[(size_t)NG * HID];       // packed Wh  [n][k]
__device__ float d_hbuf[2][BB * HID];           // ping-pong h   [b][k]
__device__ float d_cst[BB * HID];               // c state       [b][k]
__device__ int   d_bar;                         // grid barrier counter

// ---------------- helpers ----------------
__device__ __forceinline__ void fma2(ull& d, ull a, ull b) {
    asm("fma.rn.f32x2 %0, %1, %2, %0;" : "+l"(d) : "l"(a), "l"(b));
}
__device__ __forceinline__ float hsum2(ull v) {
    unsigned lo = (unsigned)(v & 0xffffffffULL);
    unsigned hi = (unsigned)(v >> 32);
    return __uint_as_float(lo) + __uint_as_float(hi);
}
__device__ __forceinline__ float sigf(float x) {
    return 1.0f / (1.0f + __expf(-x));
}
__device__ __forceinline__ void cp16(void* smem_dst, const void* gsrc) {
    unsigned d = (unsigned)__cvta_generic_to_shared(smem_dst);
    asm volatile("cp.async.cg.shared.global [%0], [%1], 16;" :: "r"(d), "l"(gsrc));
}
__device__ __forceinline__ void cp_commit() {
    asm volatile("cp.async.commit_group;");
}
template <int N>
__device__ __forceinline__ void cp_wait() {
    asm volatile("cp.async.wait_group %0;" :: "n"(N));
}

// =====================================================================
// prepack: stack gate weights/biases gate-major, zero recurrent state.
// =====================================================================
__global__ void prepack_kernel(
    const float* __restrict__ W_ii, const float* __restrict__ b_ii, const float* __restrict__ W_hi,
    const float* __restrict__ W_if, const float* __restrict__ b_if, const float* __restrict__ W_hf,
    const float* __restrict__ W_ig, const float* __restrict__ b_ig, const float* __restrict__ W_hg,
    const float* __restrict__ W_io, const float* __restrict__ b_io, const float* __restrict__ W_ho)
{
    const int stride = gridDim.x * blockDim.x;
    const int tid = blockIdx.x * blockDim.x + threadIdx.x;

    if (tid == 0) d_bar = 0;

    for (int i = tid; i < NG * EMB; i += stride) {
        int n = i / EMB, k = i - n * EMB;
        int g = n >> 10, j = n & 1023;
        const float* w = (g == 0) ? W_ii : (g == 1) ? W_if : (g == 2) ? W_ig : W_io;
        d_wxp[i] = w[j * EMB + k];
    }
    for (int i = tid; i < NG * HID; i += stride) {
        int n = i >> 10, k = i & 1023;
        int g = n >> 10, j = n & 1023;
        const float* w = (g == 0) ? W_hi : (g == 1) ? W_hf : (g == 2) ? W_hg : W_ho;
        d_whp[i] = w[j * HID + k];
    }
    for (int i = tid; i < NG; i += stride) {
        int g = i >> 10, j = i & 1023;
        const float* b = (g == 0) ? b_ii : (g == 1) ? b_if : (g == 2) ? b_ig : b_io;
        d_bxp[i] = b[j];
    }
    for (int i = tid; i < BB * HID; i += stride) {
        d_hbuf[0][i] = 0.0f; d_hbuf[1][i] = 0.0f; d_cst[i] = 0.0f;
    }
}

// =====================================================================
// gx kernel: d_gx[s][n][b] = sum_e emb[x[b,s],e] * Wxp[n][e] + bxp[n]
// grid (64 ntiles, 512 s), 256 thr. Tile 64n x 64b, K=512, 128-k chunks.
// CONFLICT-FREE mapping: pitches 132/68 (== 4 mod 32), unit row offsets:
//   rows  r = nh*32 + ngrp + 8j   batch b = bh*32 + bgrp + 4p
// =====================================================================
#define GX_AS 132
#define GX_RS 68
#define GX_SMEM ((64 * GX_AS * 2) * 4)

__global__ void __launch_bounds__(256, 2) gx_kernel(const int* __restrict__ x,
                                                    const float* __restrict__ emb)
{
    extern __shared__ float sm[];
    float* shA = sm;                 // [64 b][132]
    float* shB = sm + 64 * GX_AS;    // [64 n][132]
    float* red = sm;                 // alias: [2 ks][64 r][68] = 8704 words

    const int t = threadIdx.x;
    const int s = blockIdx.y;
    const int n0 = blockIdx.x * 64;

    __shared__ int tok[64];
    if (t < 64) tok[t] = x[t * SEQ + s];

    const int w = t >> 5, lane = t & 31;
    const int ks = w & 1, bh = (w >> 1) & 1, nh = w >> 2;
    const int ngrp = lane >> 2, bgrp = lane & 3;

    ull acc[4][8];
#pragma unroll
    for (int j = 0; j < 4; j++)
#pragma unroll
        for (int p = 0; p < 8; p++) acc[j][p] = 0ULL;

    for (int ch = 0; ch < EMB; ch += 128) {
        __syncthreads();
#pragma unroll
        for (int i = 0; i < 8; i++) {
            int f = t + i * 256;
            int b = f >> 5, kq = (f & 31) * 4;
            float4 v = *(const float4*)(emb + (size_t)tok[b] * EMB + ch + kq);
            *(float4*)(shA + b * GX_AS + kq) = v;
        }
#pragma unroll
        for (int i = 0; i < 8; i++) {
            int f = t + i * 256;
            int r = f >> 5, kq = (f & 31) * 4;
            float4 v = *(const float4*)(d_wxp + (size_t)(n0 + r) * EMB + ch + kq);
            *(float4*)(shB + r * GX_AS + kq) = v;
        }
        __syncthreads();
        const int k0 = ks * 64;
#pragma unroll
        for (int kk = 0; kk < 32; kk++) {
            int kl = k0 + kk * 2;
            ull wv[4], av[8];
#pragma unroll
            for (int j = 0; j < 4; j++)
                wv[j] = *(const ull*)(shB + (nh * 32 + ngrp + 8 * j) * GX_AS + kl);
#pragma unroll
            for (int p = 0; p < 8; p++)
                av[p] = *(const ull*)(shA + (bh * 32 + bgrp + 4 * p) * GX_AS + kl);
#pragma unroll
            for (int j = 0; j < 4; j++)
#pragma unroll
                for (int p = 0; p < 8; p++)
                    fma2(acc[j][p], wv[j], av[p]);
        }
    }
    __syncthreads();
#pragma unroll
    for (int j = 0; j < 4; j++)
#pragma unroll
        for (int p = 0; p < 8; p++) {
            int r = nh * 32 + ngrp + 8 * j;
            int b = bh * 32 + bgrp + 4 * p;
            red[(ks * 64 + r) * GX_RS + b] = hsum2(acc[j][p]);
        }
    __syncthreads();
#pragma unroll
    for (int i = 0; i < 16; i++) {
        int cell = t + i * 256;
        int r = cell >> 6, b = cell & 63;
        float v = red[r * GX_RS + b] + red[(64 + r) * GX_RS + b] + d_bxp[n0 + r];
        d_gx[((size_t)s * NG + n0 + r) * BB + b] = v;
    }
}

// =====================================================================
// persistent recurrent kernel: all 512 timesteps in one launch.
// 128 CTAs x 256 threads, 1 CTA/SM. W slice (32 rows x 1024) staged in
// SMEM once. h staged per step in 128-k chunks, double-buffered via
// cp.async.cg. gx prefetched at step start. c in registers. Grid barrier.
// =====================================================================
#define PS_WS 1028                 // W row pitch (words)
#define PS_HS 132                  // h chunk row pitch (words)
#define PS_RS 68                   // reduction pitch
#define PS_SMEM ((32 * PS_WS + 2 * 64 * PS_HS) * 4)

__global__ void __launch_bounds__(256, 1) persist_kernel()
{
    extern __shared__ float sm[];
    float* shW  = sm;                            // [32 r][1028]
    float* shH0 = sm + 32 * PS_WS;               // [64 b][132]
    float* shH1 = shH0 + 64 * PS_HS;             // [64 b][132]
    float* red  = shH0;                          // [4 ks][32 r][68] = 8704 w (spans both h bufs)

    const int t = threadIdx.x;
    const int j0 = blockIdx.x * 8;
    const int w = t >> 5, lane = t & 31;
    const int ks = w & 3, bh = w >> 2;
    const int ngrp = lane >> 2, bgrp = lane & 3;

    // epilogue mapping: thread owns batch be, j-pair (2*jp, 2*jp+1)
    const int be = t & 63, jp = t >> 6;

    // ---- stage W slice once: 32 rows x 1024 k ----
#pragma unroll
    for (int i = 0; i < 32; i++) {
        int f = t + i * 256;
        int r = f >> 8, kq = (f & 255) << 2;
        int n = (r >> 3) * HID + j0 + (r & 7);   // gate = r>>3, jj = r&7
        float4 v = *(const float4*)(d_whp + (size_t)n * HID + kq);
        *(float4*)(shW + r * PS_WS + kq) = v;
    }

    float creg[2] = {0.0f, 0.0f};

    const int sb = t >> 5, skq = (t & 31) << 2;  // staging: 8 rows per pass

    for (int s = 0; s < SEQ; s++) {
        const float* __restrict__ hprev = d_hbuf[s & 1];
        float* __restrict__ hnext = d_hbuf[(s + 1) & 1];

        // ---- prefetch gate biases (gx) for this step: 2 j x 4 gates ----
        float gpre[2][4];
#pragma unroll
        for (int i = 0; i < 2; i++)
#pragma unroll
            for (int gg = 0; gg < 4; gg++)
                gpre[i][gg] = __ldg(&d_gx[((size_t)s * NG + gg * 1024 + j0 + 2 * jp + i) * BB + be]);

        ull acc[4][8];
#pragma unroll
        for (int j = 0; j < 4; j++)
#pragma unroll
            for (int p = 0; p < 8; p++) acc[j][p] = 0ULL;

        // prologue: issue chunk 0 into shH0
        __syncthreads();   // protect h buffers / red alias from previous step
#pragma unroll
        for (int i = 0; i < 8; i++) {
            int b = sb + i * 8;
            cp16(shH0 + b * PS_HS + skq, hprev + b * HID + 0 + skq);
        }
        cp_commit();

        for (int ch = 0; ch < HID; ch += 128) {
            float* cur = ((ch >> 7) & 1) ? shH1 : shH0;
            float* nxt = ((ch >> 7) & 1) ? shH0 : shH1;
            if (ch + 128 < HID) {
#pragma unroll
                for (int i = 0; i < 8; i++) {
                    int b = sb + i * 8;
                    cp16(nxt + b * PS_HS + skq, hprev + b * HID + ch + 128 + skq);
                }
                cp_commit();
                cp_wait<1>();
            } else {
                cp_wait<0>();
            }
            __syncthreads();

            const int k0 = ks * 32;
#pragma unroll
            for (int it = 0; it < 8; it++) {
                int kl = k0 + it * 4;
                ulonglong2 wv[4], hv[8];
#pragma unroll
                for (int j = 0; j < 4; j++)
                    wv[j] = *(const ulonglong2*)(shW + (ngrp + j * 8) * PS_WS + ch + kl);
#pragma unroll
                for (int p = 0; p < 8; p++)
                    hv[p] = *(const ulonglong2*)(cur + (bh * 32 + bgrp + p * 4) * PS_HS + kl);
#pragma unroll
                for (int j = 0; j < 4; j++)
#pragma unroll
                    for (int p = 0; p < 8; p++) {
                        fma2(acc[j][p], wv[j].x, hv[p].x);
                        fma2(acc[j][p], wv[j].y, hv[p].y);
                    }
            }
            __syncthreads();  // all warps done with 'cur' before it is re-filled
        }

        // ---- cross-warp k-split reduction through smem (red aliases h bufs) ----
#pragma unroll
        for (int j = 0; j < 4; j++)
#pragma unroll
            for (int p = 0; p < 8; p++) {
                int r = ngrp + j * 8;
                int b = bh * 32 + bgrp + p * 4;
                red[(ks * 32 + r) * PS_RS + b] = hsum2(acc[j][p]);
            }
        __syncthreads();

        // ---- pointwise LSTM cell update: thread = (batch be, j-pair jp) ----
        float2 hout;
#pragma unroll
        for (int i = 0; i < 2; i++) {
            int j = 2 * jp + i;
            float g[4];
#pragma unroll
            for (int gg = 0; gg < 4; gg++) {
                int r = gg * 8 + j;
                float v = red[r * PS_RS + be]
                        + red[(32 + r) * PS_RS + be]
                        + red[(64 + r) * PS_RS + be]
                        + red[(96 + r) * PS_RS + be];
                g[gg] = v + gpre[i][gg];
            }
            float it_ = sigf(g[0]);
            float ft  = sigf(g[1]);
            float gt  = tanhf(g[2]);
            float ot  = sigf(g[3]);
            float c = ft * creg[i] + it_ * gt;
            creg[i] = c;
            ((float*)&hout)[i] = ot * tanhf(c);
        }
        *(float2*)(hnext + be * HID + j0 + 2 * jp) = hout;

        // ---- grid-wide barrier ----
        __threadfence();
        __syncthreads();
        if (t == 0) {
            atomicAdd(&d_bar, 1);
            const int target = 128 * (s + 1);
            while (*(volatile int*)&d_bar < target) { }
        }
        __syncthreads();
    }

    // ---- publish final c ----
    *(float2*)(d_cst + be * HID + j0 + 2 * jp) = make_float2(creg[0], creg[1]);
}

// =====================================================================
// head: out = h @ V_w^T + V_b ; also emit h, c into d_out.
// d_out layout: [out(64x2), h(64x1024), c(64x1024)]
// =====================================================================
__global__ void head_kernel(const float* __restrict__ Vw, const float* __restrict__ Vb,
                            float* __restrict__ out)
{
    const float* hfin = d_hbuf[SEQ & 1];
    const int b = blockIdx.x, t = threadIdx.x;
    float s0 = 0.0f, s1 = 0.0f;
    for (int k = t; k < HID; k += 256) {
        float hv = hfin[b * HID + k];
        s0 += hv * Vw[k];
        s1 += hv * Vw[HID + k];
        out[128 + b * HID + k] = hv;
        out[128 + BB * HID + b * HID + k] = d_cst[b * HID + k];
    }
    __shared__ float r0[256], r1[256];
    r0[t] = s0; r1[t] = s1;
    __syncthreads();
    for (int off = 128; off > 0; off >>= 1) {
        if (t < off) { r0[t] += r0[t + off]; r1[t] += r1[t + off]; }
        __syncthreads();
    }
    if (t == 0) {
        out[b * 2 + 0] = r0[0] + Vb[0];
        out[b * 2 + 1] = r1[0] + Vb[1];
    }
}

// =====================================================================
extern "C" void kernel_launch(void* const* d_in, const int* in_sizes, int n_in,
                              void* d_out, int out_size)
{
    (void)in_sizes; (void)n_in; (void)out_size;
    const int*   x   = (const int*)d_in[0];
    const float* emb = (const float*)d_in[1];

    cudaFuncSetAttribute(gx_kernel,      cudaFuncAttributeMaxDynamicSharedMemorySize, GX_SMEM);
    cudaFuncSetAttribute(persist_kernel, cudaFuncAttributeMaxDynamicSharedMemorySize, PS_SMEM);

    prepack_kernel<<<1024, 256>>>(
        (const float*)d_in[2],  (const float*)d_in[3],  (const float*)d_in[4],
        (const float*)d_in[5],  (const float*)d_in[6],  (const float*)d_in[7],
        (const float*)d_in[8],  (const float*)d_in[9],  (const float*)d_in[10],
        (const float*)d_in[11], (const float*)d_in[12], (const float*)d_in[13]);

    gx_kernel<<<dim3(64, 512), 256, GX_SMEM>>>(x, emb);

    persist_kernel<<<128, 256, PS_SMEM>>>();

    head_kernel<<<BB, 256>>>((const float*)d_in[14], (const float*)d_in[15], (float*)d_out);
}